// round 7
// baseline (speedup 1.0000x reference)
#include <cuda_runtime.h>
#include <cuda_fp16.h>
#include <cstdint>

#define BB 4
#define SS 2048
#define DD 1024
#define MTOT (BB*SS)   // 8192

// Static device scratch
__device__ __half g_X [(long)MTOT*DD];
__device__ __half g_Y [(long)MTOT*DD];
__device__ __half g_Z [(long)MTOT*DD];
__device__ __half g_W [3][(long)DD*DD];
__device__ __half g_Q [(long)MTOT*DD];
__device__ __half g_K [(long)MTOT*DD];
__device__ __half g_Vt[(long)BB*DD*SS];    // V transposed: [b][d][s]
__device__ __half g_P [(long)BB*SS*SS];    // exp(scores) fp16 (unnormalized)
__device__ float  g_RS[MTOT];              // per-row sums of exp

// Tile geometry: CTA 128x256, warp 64x64 (2x4 warp grid), BK=64 halves.
#define STAGES   4
#define A_BYTES  16384u            // 128 rows * 128B
#define B_BYTES  32768u            // 256 rows * 128B
#define STG      (A_BYTES + B_BYTES)
#define SMEMSZ   (STAGES * STG)    // 192 KB

// ---------------------------------------------------------------------------
// helpers
// ---------------------------------------------------------------------------
__device__ __forceinline__ uint32_t smem_u32(const void* p) {
    uint32_t a;
    asm("{ .reg .u64 t; cvta.to.shared.u64 t, %1; cvt.u32.u64 %0, t; }"
        : "=r"(a) : "l"(p));
    return a;
}
__device__ __forceinline__ void cp16(uint32_t s, const void* g) {
    asm volatile("cp.async.cg.shared.global [%0], [%1], 16;" :: "r"(s), "l"(g));
}

#define LDSM4(r, addr) \
    asm volatile("ldmatrix.sync.aligned.m8n8.x4.shared.b16 {%0,%1,%2,%3}, [%4];" \
        : "=r"((r)[0]), "=r"((r)[1]), "=r"((r)[2]), "=r"((r)[3]) : "r"(addr))

#define MMA_F16(c, a, b0, b1) \
    asm volatile("mma.sync.aligned.m16n8k16.row.col.f32.f16.f16.f32 " \
        "{%0,%1,%2,%3}, {%4,%5,%6,%7}, {%8,%9}, {%0,%1,%2,%3};" \
        : "+f"((c)[0]), "+f"((c)[1]), "+f"((c)[2]), "+f"((c)[3]) \
        : "r"((a)[0]), "r"((a)[1]), "r"((a)[2]), "r"((a)[3]), "r"(b0), "r"(b1))

// ---------------------------------------------------------------------------
// fp32 -> fp16 conversion (3 tensors via blockIdx.z); 8 floats per thread.
// ---------------------------------------------------------------------------
__global__ void cvt3_half(const float4* __restrict__ i0, __half* __restrict__ o0,
                          const float4* __restrict__ i1, __half* __restrict__ o1,
                          const float4* __restrict__ i2, __half* __restrict__ o2)
{
    const long i = blockIdx.x * (long)blockDim.x + threadIdx.x;
    const float4* in;
    __half* out;
    if (blockIdx.z == 0)      { in = i0; out = o0; }
    else if (blockIdx.z == 1) { in = i1; out = o1; }
    else                      { in = i2; out = o2; }
    float4 a = in[2 * i], b = in[2 * i + 1];
    __half2 h[4];
    h[0] = __floats2half2_rn(a.x, a.y);
    h[1] = __floats2half2_rn(a.z, a.w);
    h[2] = __floats2half2_rn(b.x, b.y);
    h[3] = __floats2half2_rn(b.z, b.w);
    *(uint4*)(out + 8 * i) = *(uint4*)h;
}

__global__ void zero_rs(float* __restrict__ rs)
{
    rs[blockIdx.x * 1024 + threadIdx.x] = 0.0f;
}

// ---------------------------------------------------------------------------
// Shared mainloop for one 128x256 tile: acc = A[128,K] @ B[256,K]^T
// A,B half K-contiguous; SW128 128B rows; 4-stage cp.async; fp32 acc.
// Caller must __syncthreads() before reuse of smem across tiles (done here
// at entry).
// ---------------------------------------------------------------------------
__device__ __forceinline__ void mainloop(
    const __half* __restrict__ A, const __half* __restrict__ B,
    int K, int lda, int ldb, uint32_t sbase,
    int tid, int lane, int wm, int wn, float acc[4][8][4])
{
    __syncthreads();   // previous tile's readers done before overwriting smem

    auto issue = [&](int kt, int st) {
        const uint32_t s0 = sbase + (uint32_t)st * STG;
        const __half* a = A + (long)kt * 64;
        const __half* b = B + (long)kt * 64;
#pragma unroll
        for (int i = 0; i < 4; i++) {
            const int idx = i * 256 + tid;
            const int row = idx >> 3;
            const int c   = idx & 7;
            const uint32_t off = (uint32_t)row * 128u + (uint32_t)c * 16u;
            cp16(s0 + (off ^ ((off >> 3) & 0x70u)), a + (long)row * lda + c * 8);
        }
#pragma unroll
        for (int i = 0; i < 8; i++) {
            const int idx = i * 256 + tid;
            const int row = idx >> 3;
            const int c   = idx & 7;
            const uint32_t off = (uint32_t)row * 128u + (uint32_t)c * 16u;
            cp16(s0 + A_BYTES + (off ^ ((off >> 3) & 0x70u)),
                 b + (long)row * ldb + c * 8);
        }
        asm volatile("cp.async.commit_group;" ::: "memory");
    };

    const int r16 = lane & 15;
    const uint32_t hi16 = (uint32_t)(lane >> 4) * 16u;
    uint32_t aBase[4], aXor[4], bBase[4], bXor[4];
#pragma unroll
    for (int mt = 0; mt < 4; mt++) {
        const int row = wm * 64 + mt * 16 + r16;
        aBase[mt] = (uint32_t)row * 128u;
        aXor[mt]  = ((uint32_t)(row & 7) << 4);
    }
#pragma unroll
    for (int p = 0; p < 4; p++) {
        const int row = wn * 64 + p * 16 + r16;
        bBase[p] = A_BYTES + (uint32_t)row * 128u;
        bXor[p]  = ((uint32_t)(row & 7) << 4);
    }

    const int KT = K >> 6;
#pragma unroll
    for (int s = 0; s < STAGES - 1; s++) issue(s, s);

    for (int kt = 0; kt < KT; kt++) {
        asm volatile("cp.async.wait_group %0;" :: "n"(STAGES - 2));
        __syncthreads();

        const int pf = kt + STAGES - 1;
        if (pf < KT) issue(pf, pf & 3);
        else asm volatile("cp.async.commit_group;" ::: "memory");

        const uint32_t base = sbase + (uint32_t)(kt & 3) * STG;

#pragma unroll
        for (int kc = 0; kc < 4; kc++) {
            const uint32_t kb = (uint32_t)kc * 32u + hi16;
            uint32_t af[4][4], bf[4][4];
#pragma unroll
            for (int mt = 0; mt < 4; mt++)
                LDSM4(af[mt], base + aBase[mt] + (kb ^ aXor[mt]));
#pragma unroll
            for (int p = 0; p < 4; p++)
                LDSM4(bf[p],  base + bBase[p] + (kb ^ bXor[p]));

#pragma unroll
            for (int mt = 0; mt < 4; mt++)
#pragma unroll
                for (int nt = 0; nt < 8; nt++)
                    MMA_F16(acc[mt][nt], af[mt],
                            bf[nt >> 1][nt & 1],
                            bf[nt >> 1][(nt & 1) + 2]);
        }
    }
}

// n-offset within the warp's 64-col slab for fragment nt
__device__ __forceinline__ int n_off(int nt, int tg) {
    return (nt >> 1) * 16 + (nt & 1) * 8 + tg * 2;
}

// ---------------------------------------------------------------------------
// Persistent QKV projection. Tiles: z(3) x by(64) x bx(4) = 768.
// z==2 (V): transposed store Vt[(b*DD + n)*SS + s].
// ---------------------------------------------------------------------------
__global__ __launch_bounds__(256, 1)
void gemm_proj(const __half* __restrict__ Ax, const __half* __restrict__ Ay,
               const __half* __restrict__ Az, const __half* __restrict__ W,
               const float* __restrict__ b0, const float* __restrict__ b1,
               const float* __restrict__ b2,
               __half* __restrict__ Qo, __half* __restrict__ Ko,
               __half* __restrict__ Vt)
{
    extern __shared__ __align__(1024) char smem[];
    const uint32_t sbase = smem_u32(smem);
    const int tid  = threadIdx.x;
    const int lane = tid & 31;
    const int wid  = tid >> 5;
    const int wm   = wid & 1;
    const int wn   = wid >> 1;

    for (int t = blockIdx.x; t < 768; t += gridDim.x) {
        const int z   = t >> 8;
        const int rem = t & 255;
        const int bm  = (rem >> 2) * 128;
        const int bn  = (rem & 3) * 256;

        const __half* A = ((z == 0) ? Ax : (z == 1) ? Ay : Az) + (long)bm * DD;
        const __half* B = W + (long)z * DD * DD + (long)bn * DD;
        const float* bias = (z == 0) ? b0 : (z == 1) ? b1 : b2;

        float acc[4][8][4];
#pragma unroll
        for (int mt = 0; mt < 4; mt++)
#pragma unroll
            for (int nt = 0; nt < 8; nt++)
#pragma unroll
                for (int i = 0; i < 4; i++) acc[mt][nt][i] = 0.0f;

        mainloop(A, B, DD, DD, DD, sbase, tid, lane, wm, wn, acc);

        const int g  = lane >> 2;
        const int tg = lane & 3;
#pragma unroll
        for (int mt = 0; mt < 4; mt++) {
#pragma unroll
            for (int nt = 0; nt < 8; nt++) {
                const int n = bn + wn * 64 + n_off(nt, tg);
                float2 bv = *(const float2*)(bias + n);
#pragma unroll
                for (int h = 0; h < 2; h++) {
                    const int m = bm + wm * 64 + mt * 16 + g + h * 8;
                    const float v0 = acc[mt][nt][h * 2 + 0] + bv.x;
                    const float v1 = acc[mt][nt][h * 2 + 1] + bv.y;
                    if (z == 2) {
                        const int b = m >> 11;
                        const int s = m & (SS - 1);
                        const long o = ((long)b * DD + n) * SS + s;
                        Vt[o]      = __float2half_rn(v0);
                        Vt[o + SS] = __float2half_rn(v1);
                    } else {
                        __half* C = (z == 0) ? Qo : Ko;
                        *(__half2*)(C + (long)m * DD + n) = __floats2half2_rn(v0, v1);
                    }
                }
            }
        }
    }
}

// ---------------------------------------------------------------------------
// Persistent scores: P = exp(Q K^T / 32) fp16 + atomic row sums.
// Tiles: bz(4) x by(16) x bx(8) = 512.
// ---------------------------------------------------------------------------
__global__ __launch_bounds__(256, 1)
void gemm_scores(const __half* __restrict__ Q, const __half* __restrict__ Kb,
                 __half* __restrict__ P, float* __restrict__ RS)
{
    extern __shared__ __align__(1024) char smem[];
    const uint32_t sbase = smem_u32(smem);
    const int tid  = threadIdx.x;
    const int lane = tid & 31;
    const int wid  = tid >> 5;
    const int wm   = wid & 1;
    const int wn   = wid >> 1;

    for (int t = blockIdx.x; t < 512; t += gridDim.x) {
        const long bz = t >> 7;
        const int rem = t & 127;
        const int bm  = (rem >> 3) * 128;
        const int bn  = (rem & 7) * 256;

        const __half* A = Q  + bz * SS * DD + (long)bm * DD;
        const __half* B = Kb + bz * SS * DD + (long)bn * DD;
        __half* Pb = P + bz * (long)SS * SS;
        float* rs = RS + bz * SS;

        float acc[4][8][4];
#pragma unroll
        for (int mt = 0; mt < 4; mt++)
#pragma unroll
            for (int nt = 0; nt < 8; nt++)
#pragma unroll
                for (int i = 0; i < 4; i++) acc[mt][nt][i] = 0.0f;

        mainloop(A, B, DD, DD, DD, sbase, tid, lane, wm, wn, acc);

        const int g  = lane >> 2;
        const int tg = lane & 3;
#pragma unroll
        for (int mt = 0; mt < 4; mt++) {
            float s0 = 0.0f, s1 = 0.0f;
            const int m0 = bm + wm * 64 + mt * 16 + g;
#pragma unroll
            for (int nt = 0; nt < 8; nt++) {
                const int n = bn + wn * 64 + n_off(nt, tg);
                const float e00 = __expf(acc[mt][nt][0] * 0.03125f);
                const float e01 = __expf(acc[mt][nt][1] * 0.03125f);
                const float e10 = __expf(acc[mt][nt][2] * 0.03125f);
                const float e11 = __expf(acc[mt][nt][3] * 0.03125f);
                s0 += e00 + e01;
                s1 += e10 + e11;
                *(__half2*)(Pb + (long)m0 * SS + n)       = __floats2half2_rn(e00, e01);
                *(__half2*)(Pb + (long)(m0 + 8) * SS + n) = __floats2half2_rn(e10, e11);
            }
            s0 += __shfl_xor_sync(~0u, s0, 1);
            s0 += __shfl_xor_sync(~0u, s0, 2);
            s1 += __shfl_xor_sync(~0u, s1, 1);
            s1 += __shfl_xor_sync(~0u, s1, 2);
            if (tg == 0) {
                atomicAdd(&rs[m0],     s0);
                atomicAdd(&rs[m0 + 8], s1);
            }
        }
    }
}

// ---------------------------------------------------------------------------
// Persistent PV: out = (P @ Vt^T) / rowsum, fp32 out.
// Tiles: bz(4) x by(16) x bx(4) = 256.
// ---------------------------------------------------------------------------
__global__ __launch_bounds__(256, 1)
void gemm_pv(const __half* __restrict__ P, const __half* __restrict__ Vt,
             const float* __restrict__ RS, float* __restrict__ O)
{
    extern __shared__ __align__(1024) char smem[];
    const uint32_t sbase = smem_u32(smem);
    const int tid  = threadIdx.x;
    const int lane = tid & 31;
    const int wid  = tid >> 5;
    const int wm   = wid & 1;
    const int wn   = wid >> 1;

    for (int t = blockIdx.x; t < 256; t += gridDim.x) {
        const long bz = t >> 6;
        const int bm  = ((t >> 2) & 15) * 128;
        const int bn  = (t & 3) * 256;

        const __half* A = P  + bz * (long)SS * SS + (long)bm * SS;
        const __half* B = Vt + bz * (long)DD * SS + (long)bn * SS;
        const float* rs = RS + bz * SS;
        float* C = O + bz * (long)SS * DD;

        float acc[4][8][4];
#pragma unroll
        for (int mt = 0; mt < 4; mt++)
#pragma unroll
            for (int nt = 0; nt < 8; nt++)
#pragma unroll
                for (int i = 0; i < 4; i++) acc[mt][nt][i] = 0.0f;

        mainloop(A, B, SS, SS, SS, sbase, tid, lane, wm, wn, acc);

        const int g  = lane >> 2;
        const int tg = lane & 3;
#pragma unroll
        for (int mt = 0; mt < 4; mt++) {
            const int m0 = bm + wm * 64 + mt * 16 + g;
            const float i0 = 1.0f / __ldg(&rs[m0]);
            const float i1 = 1.0f / __ldg(&rs[m0 + 8]);
#pragma unroll
            for (int nt = 0; nt < 8; nt++) {
                const int n = bn + wn * 64 + n_off(nt, tg);
                float2 v0, v1;
                v0.x = acc[mt][nt][0] * i0;
                v0.y = acc[mt][nt][1] * i0;
                v1.x = acc[mt][nt][2] * i1;
                v1.y = acc[mt][nt][3] * i1;
                *(float2*)(C + (long)m0 * DD + n)       = v0;
                *(float2*)(C + (long)(m0 + 8) * DD + n) = v1;
            }
        }
    }
}

extern "C" void kernel_launch(void* const* d_in, const int* in_sizes, int n_in,
                              void* d_out, int out_size)
{
    const float* x  = (const float*)d_in[0];
    const float* y  = (const float*)d_in[1];
    const float* z  = (const float*)d_in[2];
    const float* Wq = (const float*)d_in[3];
    const float* bq = (const float*)d_in[4];
    const float* Wk = (const float*)d_in[5];
    const float* bk = (const float*)d_in[6];
    const float* Wv = (const float*)d_in[7];
    const float* bv = (const float*)d_in[8];
    float* out = (float*)d_out;

    void *pX, *pY, *pZ, *pW, *pQ, *pK, *pV, *pP, *pRS;
    cudaGetSymbolAddress(&pX,  g_X);
    cudaGetSymbolAddress(&pY,  g_Y);
    cudaGetSymbolAddress(&pZ,  g_Z);
    cudaGetSymbolAddress(&pW,  g_W);
    cudaGetSymbolAddress(&pQ,  g_Q);
    cudaGetSymbolAddress(&pK,  g_K);
    cudaGetSymbolAddress(&pV,  g_Vt);
    cudaGetSymbolAddress(&pP,  g_P);
    cudaGetSymbolAddress(&pRS, g_RS);
    __half* X  = (__half*)pX;
    __half* Y  = (__half*)pY;
    __half* Z  = (__half*)pZ;
    __half* W  = (__half*)pW;
    __half* Q  = (__half*)pQ;
    __half* Kb = (__half*)pK;
    __half* Vt = (__half*)pV;
    __half* P  = (__half*)pP;
    float*  RS = (float*)pRS;

    int nsm = 148;
    cudaDeviceGetAttribute(&nsm, cudaDevAttrMultiProcessorCount, 0);

    cudaFuncSetAttribute(gemm_proj,   cudaFuncAttributeMaxDynamicSharedMemorySize, SMEMSZ);
    cudaFuncSetAttribute(gemm_scores, cudaFuncAttributeMaxDynamicSharedMemorySize, SMEMSZ);
    cudaFuncSetAttribute(gemm_pv,     cudaFuncAttributeMaxDynamicSharedMemorySize, SMEMSZ);

    // 0) zero row sums + convert inputs to fp16
    zero_rs<<<MTOT / 1024, 1024>>>(RS);
    {
        dim3 gb((MTOT * (long)DD) / (8 * 256), 1, 3);
        cvt3_half<<<gb, 256>>>((const float4*)x, X,
                               (const float4*)y, Y,
                               (const float4*)z, Z);
        dim3 gw(((long)DD * DD) / (8 * 256), 1, 3);
        cvt3_half<<<gw, 256>>>((const float4*)Wq, W,
                               (const float4*)Wk, W + (long)DD * DD,
                               (const float4*)Wv, W + 2 * (long)DD * DD);
    }
    // 1) merged persistent QKV projections (V transposed)
    gemm_proj<<<nsm, 256, SMEMSZ>>>(X, Y, Z, W, bq, bk, bv, Q, Kb, Vt);
    // 2) P = exp(Q K^T / 32), row sums via atomics
    gemm_scores<<<nsm, 256, SMEMSZ>>>(Q, Kb, P, RS);
    // 3) out = (P @ Vt^T) / rowsum
    gemm_pv<<<nsm, 256, SMEMSZ>>>(P, Vt, RS, out);
}

// round 8
// speedup vs baseline: 1.1058x; 1.1058x over previous
#include <cuda_runtime.h>
#include <cuda_fp16.h>
#include <cstdint>

#define BB 4
#define SS 2048
#define DD 1024
#define MTOT (BB*SS)   // 8192

// Static device scratch
__device__ __half g_X [(long)MTOT*DD];
__device__ __half g_Y [(long)MTOT*DD];
__device__ __half g_Z [(long)MTOT*DD];
__device__ __half g_W [3][(long)DD*DD];
__device__ __half g_Q [(long)MTOT*DD];
__device__ __half g_K [(long)MTOT*DD];
__device__ __half g_Vt[(long)BB*DD*SS];    // V transposed: [b][d][s]
__device__ __half g_P [(long)BB*SS*SS];    // exp(scores) fp16 (unnormalized)
__device__ float  g_RS[MTOT];              // per-row sums of exp

// Tile geometry: CTA 128x128, 4 warps (2x2), warp tile 64x64, BK=64 halves.
#define NTHR     128
#define STAGES   3
#define A_BYTES  16384u            // 128 rows * 128B
#define B_BYTES  16384u
#define STG      (A_BYTES + B_BYTES)
#define SMEMSZ   (STAGES * STG)    // 96 KB -> 2 CTAs/SM

// ---------------------------------------------------------------------------
// helpers
// ---------------------------------------------------------------------------
__device__ __forceinline__ uint32_t smem_u32(const void* p) {
    uint32_t a;
    asm("{ .reg .u64 t; cvta.to.shared.u64 t, %1; cvt.u32.u64 %0, t; }"
        : "=r"(a) : "l"(p));
    return a;
}
__device__ __forceinline__ void cp16(uint32_t s, const void* g) {
    asm volatile("cp.async.cg.shared.global [%0], [%1], 16;" :: "r"(s), "l"(g));
}

#define LDSM4(r, addr) \
    asm volatile("ldmatrix.sync.aligned.m8n8.x4.shared.b16 {%0,%1,%2,%3}, [%4];" \
        : "=r"((r)[0]), "=r"((r)[1]), "=r"((r)[2]), "=r"((r)[3]) : "r"(addr))

#define MMA_F16(c, a, b0, b1) \
    asm volatile("mma.sync.aligned.m16n8k16.row.col.f32.f16.f16.f32 " \
        "{%0,%1,%2,%3}, {%4,%5,%6,%7}, {%8,%9}, {%0,%1,%2,%3};" \
        : "+f"((c)[0]), "+f"((c)[1]), "+f"((c)[2]), "+f"((c)[3]) \
        : "r"((a)[0]), "r"((a)[1]), "r"((a)[2]), "r"((a)[3]), "r"(b0), "r"(b1))

// ---------------------------------------------------------------------------
// fp32 -> fp16 conversion (3 tensors via blockIdx.z); 8 floats per thread.
// ---------------------------------------------------------------------------
__global__ void cvt3_half(const float4* __restrict__ i0, __half* __restrict__ o0,
                          const float4* __restrict__ i1, __half* __restrict__ o1,
                          const float4* __restrict__ i2, __half* __restrict__ o2)
{
    const long i = blockIdx.x * (long)blockDim.x + threadIdx.x;
    const float4* in;
    __half* out;
    if (blockIdx.z == 0)      { in = i0; out = o0; }
    else if (blockIdx.z == 1) { in = i1; out = o1; }
    else                      { in = i2; out = o2; }
    float4 a = in[2 * i], b = in[2 * i + 1];
    __half2 h[4];
    h[0] = __floats2half2_rn(a.x, a.y);
    h[1] = __floats2half2_rn(a.z, a.w);
    h[2] = __floats2half2_rn(b.x, b.y);
    h[3] = __floats2half2_rn(b.z, b.w);
    *(uint4*)(out + 8 * i) = *(uint4*)h;
}

__global__ void zero_rs(float* __restrict__ rs)
{
    rs[blockIdx.x * 1024 + threadIdx.x] = 0.0f;
}

// ---------------------------------------------------------------------------
// Mainloop for one 128x128 tile: acc[4][8][4] += A[128,K] @ B[128,K]^T
// A,B half K-contiguous; SW128 128B rows; 3-stage cp.async; 4 warps (2x2),
// warp tile 64x64. __syncthreads at entry protects smem reuse across tiles.
// ---------------------------------------------------------------------------
__device__ __forceinline__ void mainloop(
    const __half* __restrict__ A, const __half* __restrict__ B,
    int K, int lda, int ldb, uint32_t sbase,
    int tid, int lane, int wm, int wn, float acc[4][8][4])
{
    __syncthreads();

    auto issue = [&](int kt, int st) {
        const uint32_t s0 = sbase + (uint32_t)st * STG;
        const __half* a = A + (long)kt * 64;
        const __half* b = B + (long)kt * 64;
#pragma unroll
        for (int i = 0; i < 8; i++) {
            const int idx = i * NTHR + tid;
            const int row = idx >> 3;
            const int c   = idx & 7;
            const uint32_t off = (uint32_t)row * 128u + (uint32_t)c * 16u;
            cp16(s0 + (off ^ ((off >> 3) & 0x70u)), a + (long)row * lda + c * 8);
        }
#pragma unroll
        for (int i = 0; i < 8; i++) {
            const int idx = i * NTHR + tid;
            const int row = idx >> 3;
            const int c   = idx & 7;
            const uint32_t off = (uint32_t)row * 128u + (uint32_t)c * 16u;
            cp16(s0 + A_BYTES + (off ^ ((off >> 3) & 0x70u)),
                 b + (long)row * ldb + c * 8);
        }
        asm volatile("cp.async.commit_group;" ::: "memory");
    };

    const int r16 = lane & 15;
    const uint32_t hi16 = (uint32_t)(lane >> 4) * 16u;
    uint32_t aBase[4], aXor[4], bBase[4], bXor[4];
#pragma unroll
    for (int mt = 0; mt < 4; mt++) {
        const int row = wm * 64 + mt * 16 + r16;
        aBase[mt] = (uint32_t)row * 128u;
        aXor[mt]  = ((uint32_t)(row & 7) << 4);
    }
#pragma unroll
    for (int p = 0; p < 4; p++) {
        const int row = wn * 64 + p * 16 + r16;
        bBase[p] = A_BYTES + (uint32_t)row * 128u;
        bXor[p]  = ((uint32_t)(row & 7) << 4);
    }

    const int KT = K >> 6;
#pragma unroll
    for (int s = 0; s < STAGES - 1; s++) issue(s, s);

    for (int kt = 0; kt < KT; kt++) {
        asm volatile("cp.async.wait_group %0;" :: "n"(STAGES - 2));
        __syncthreads();

        const int pf = kt + STAGES - 1;
        if (pf < KT) issue(pf, pf % STAGES);
        else asm volatile("cp.async.commit_group;" ::: "memory");

        const uint32_t base = sbase + (uint32_t)(kt % STAGES) * STG;

#pragma unroll
        for (int kc = 0; kc < 4; kc++) {
            const uint32_t kb = (uint32_t)kc * 32u + hi16;
            uint32_t af[4][4], bf[4][4];
#pragma unroll
            for (int mt = 0; mt < 4; mt++)
                LDSM4(af[mt], base + aBase[mt] + (kb ^ aXor[mt]));
#pragma unroll
            for (int p = 0; p < 4; p++)
                LDSM4(bf[p],  base + bBase[p] + (kb ^ bXor[p]));

#pragma unroll
            for (int mt = 0; mt < 4; mt++)
#pragma unroll
                for (int nt = 0; nt < 8; nt++)
                    MMA_F16(acc[mt][nt], af[mt],
                            bf[nt >> 1][nt & 1],
                            bf[nt >> 1][(nt & 1) + 2]);
        }
    }
}

__device__ __forceinline__ int n_off(int nt, int tg) {
    return (nt >> 1) * 16 + (nt & 1) * 8 + tg * 2;
}

// ---------------------------------------------------------------------------
// Persistent QKV projection. Tiles: z(3) x 64(m) x 8(n) = 1536.
// z==2 (V): transposed store Vt[(b*DD + n)*SS + s].
// ---------------------------------------------------------------------------
__global__ __launch_bounds__(NTHR, 2)
void gemm_proj(const __half* __restrict__ Ax, const __half* __restrict__ Ay,
               const __half* __restrict__ Az, const __half* __restrict__ W,
               const float* __restrict__ b0, const float* __restrict__ b1,
               const float* __restrict__ b2,
               __half* __restrict__ Qo, __half* __restrict__ Ko,
               __half* __restrict__ Vt)
{
    extern __shared__ __align__(1024) char smem[];
    const uint32_t sbase = smem_u32(smem);
    const int tid  = threadIdx.x;
    const int lane = tid & 31;
    const int wid  = tid >> 5;
    const int wm   = wid & 1;
    const int wn   = wid >> 1;   // 0..1

    for (int t = blockIdx.x; t < 1536; t += gridDim.x) {
        const int z   = t >> 9;
        const int rem = t & 511;
        const int bm  = (rem >> 3) * 128;
        const int bn  = (rem & 7) * 128;

        const __half* A = ((z == 0) ? Ax : (z == 1) ? Ay : Az) + (long)bm * DD;
        const __half* B = W + (long)z * DD * DD + (long)bn * DD;
        const float* bias = (z == 0) ? b0 : (z == 1) ? b1 : b2;

        float acc[4][8][4];
#pragma unroll
        for (int mt = 0; mt < 4; mt++)
#pragma unroll
            for (int nt = 0; nt < 8; nt++)
#pragma unroll
                for (int i = 0; i < 4; i++) acc[mt][nt][i] = 0.0f;

        mainloop(A, B, DD, DD, DD, sbase, tid, lane, wm, wn, acc);

        const int g  = lane >> 2;
        const int tg = lane & 3;
#pragma unroll
        for (int mt = 0; mt < 4; mt++) {
#pragma unroll
            for (int nt = 0; nt < 8; nt++) {
                const int n = bn + wn * 64 + n_off(nt, tg);
                float2 bv = *(const float2*)(bias + n);
#pragma unroll
                for (int h = 0; h < 2; h++) {
                    const int m = bm + wm * 64 + mt * 16 + g + h * 8;
                    const float v0 = acc[mt][nt][h * 2 + 0] + bv.x;
                    const float v1 = acc[mt][nt][h * 2 + 1] + bv.y;
                    if (z == 2) {
                        const int b = m >> 11;
                        const int s = m & (SS - 1);
                        const long o = ((long)b * DD + n) * SS + s;
                        Vt[o]      = __float2half_rn(v0);
                        Vt[o + SS] = __float2half_rn(v1);
                    } else {
                        __half* C = (z == 0) ? Qo : Ko;
                        *(__half2*)(C + (long)m * DD + n) = __floats2half2_rn(v0, v1);
                    }
                }
            }
        }
    }
}

// ---------------------------------------------------------------------------
// Persistent scores: P = exp(Q K^T / 32) fp16 + atomic row sums.
// Tiles: bz(4) x 16(m) x 16(n) = 1024.
// ---------------------------------------------------------------------------
__global__ __launch_bounds__(NTHR, 2)
void gemm_scores(const __half* __restrict__ Q, const __half* __restrict__ Kb,
                 __half* __restrict__ P, float* __restrict__ RS)
{
    extern __shared__ __align__(1024) char smem[];
    const uint32_t sbase = smem_u32(smem);
    const int tid  = threadIdx.x;
    const int lane = tid & 31;
    const int wid  = tid >> 5;
    const int wm   = wid & 1;
    const int wn   = wid >> 1;

    for (int t = blockIdx.x; t < 1024; t += gridDim.x) {
        const long bz = t >> 8;
        const int bm  = ((t >> 4) & 15) * 128;
        const int bn  = (t & 15) * 128;

        const __half* A = Q  + bz * SS * DD + (long)bm * DD;
        const __half* B = Kb + bz * SS * DD + (long)bn * DD;
        __half* Pb = P + bz * (long)SS * SS;
        float* rs = RS + bz * SS;

        float acc[4][8][4];
#pragma unroll
        for (int mt = 0; mt < 4; mt++)
#pragma unroll
            for (int nt = 0; nt < 8; nt++)
#pragma unroll
                for (int i = 0; i < 4; i++) acc[mt][nt][i] = 0.0f;

        mainloop(A, B, DD, DD, DD, sbase, tid, lane, wm, wn, acc);

        const int g  = lane >> 2;
        const int tg = lane & 3;
#pragma unroll
        for (int mt = 0; mt < 4; mt++) {
            float s0 = 0.0f, s1 = 0.0f;
            const int m0 = bm + wm * 64 + mt * 16 + g;
#pragma unroll
            for (int nt = 0; nt < 8; nt++) {
                const int n = bn + wn * 64 + n_off(nt, tg);
                const float e00 = __expf(acc[mt][nt][0] * 0.03125f);
                const float e01 = __expf(acc[mt][nt][1] * 0.03125f);
                const float e10 = __expf(acc[mt][nt][2] * 0.03125f);
                const float e11 = __expf(acc[mt][nt][3] * 0.03125f);
                s0 += e00 + e01;
                s1 += e10 + e11;
                *(__half2*)(Pb + (long)m0 * SS + n)       = __floats2half2_rn(e00, e01);
                *(__half2*)(Pb + (long)(m0 + 8) * SS + n) = __floats2half2_rn(e10, e11);
            }
            s0 += __shfl_xor_sync(~0u, s0, 1);
            s0 += __shfl_xor_sync(~0u, s0, 2);
            s1 += __shfl_xor_sync(~0u, s1, 1);
            s1 += __shfl_xor_sync(~0u, s1, 2);
            if (tg == 0) {
                atomicAdd(&rs[m0],     s0);
                atomicAdd(&rs[m0 + 8], s1);
            }
        }
    }
}

// ---------------------------------------------------------------------------
// Persistent PV: out = (P @ Vt^T) / rowsum, fp32 out.
// Tiles: bz(4) x 16(m) x 8(n) = 512.
// ---------------------------------------------------------------------------
__global__ __launch_bounds__(NTHR, 2)
void gemm_pv(const __half* __restrict__ P, const __half* __restrict__ Vt,
             const float* __restrict__ RS, float* __restrict__ O)
{
    extern __shared__ __align__(1024) char smem[];
    const uint32_t sbase = smem_u32(smem);
    const int tid  = threadIdx.x;
    const int lane = tid & 31;
    const int wid  = tid >> 5;
    const int wm   = wid & 1;
    const int wn   = wid >> 1;

    for (int t = blockIdx.x; t < 512; t += gridDim.x) {
        const long bz = t >> 7;
        const int bm  = ((t >> 3) & 15) * 128;
        const int bn  = (t & 7) * 128;

        const __half* A = P  + bz * (long)SS * SS + (long)bm * SS;
        const __half* B = Vt + bz * (long)DD * SS + (long)bn * SS;
        const float* rs = RS + bz * SS;
        float* C = O + bz * (long)SS * DD;

        float acc[4][8][4];
#pragma unroll
        for (int mt = 0; mt < 4; mt++)
#pragma unroll
            for (int nt = 0; nt < 8; nt++)
#pragma unroll
                for (int i = 0; i < 4; i++) acc[mt][nt][i] = 0.0f;

        mainloop(A, B, SS, SS, SS, sbase, tid, lane, wm, wn, acc);

        const int g  = lane >> 2;
        const int tg = lane & 3;
#pragma unroll
        for (int mt = 0; mt < 4; mt++) {
            const int m0 = bm + wm * 64 + mt * 16 + g;
            const float i0 = 1.0f / __ldg(&rs[m0]);
            const float i1 = 1.0f / __ldg(&rs[m0 + 8]);
#pragma unroll
            for (int nt = 0; nt < 8; nt++) {
                const int n = bn + wn * 64 + n_off(nt, tg);
                float2 v0, v1;
                v0.x = acc[mt][nt][0] * i0;
                v0.y = acc[mt][nt][1] * i0;
                v1.x = acc[mt][nt][2] * i1;
                v1.y = acc[mt][nt][3] * i1;
                *(float2*)(C + (long)m0 * DD + n)       = v0;
                *(float2*)(C + (long)(m0 + 8) * DD + n) = v1;
            }
        }
    }
}

extern "C" void kernel_launch(void* const* d_in, const int* in_sizes, int n_in,
                              void* d_out, int out_size)
{
    const float* x  = (const float*)d_in[0];
    const float* y  = (const float*)d_in[1];
    const float* z  = (const float*)d_in[2];
    const float* Wq = (const float*)d_in[3];
    const float* bq = (const float*)d_in[4];
    const float* Wk = (const float*)d_in[5];
    const float* bk = (const float*)d_in[6];
    const float* Wv = (const float*)d_in[7];
    const float* bv = (const float*)d_in[8];
    float* out = (float*)d_out;

    void *pX, *pY, *pZ, *pW, *pQ, *pK, *pV, *pP, *pRS;
    cudaGetSymbolAddress(&pX,  g_X);
    cudaGetSymbolAddress(&pY,  g_Y);
    cudaGetSymbolAddress(&pZ,  g_Z);
    cudaGetSymbolAddress(&pW,  g_W);
    cudaGetSymbolAddress(&pQ,  g_Q);
    cudaGetSymbolAddress(&pK,  g_K);
    cudaGetSymbolAddress(&pV,  g_Vt);
    cudaGetSymbolAddress(&pP,  g_P);
    cudaGetSymbolAddress(&pRS, g_RS);
    __half* X  = (__half*)pX;
    __half* Y  = (__half*)pY;
    __half* Z  = (__half*)pZ;
    __half* W  = (__half*)pW;
    __half* Q  = (__half*)pQ;
    __half* Kb = (__half*)pK;
    __half* Vt = (__half*)pV;
    __half* P  = (__half*)pP;
    float*  RS = (float*)pRS;

    int nsm = 148;
    cudaDeviceGetAttribute(&nsm, cudaDevAttrMultiProcessorCount, 0);
    const int grid = 2 * nsm;

    cudaFuncSetAttribute(gemm_proj,   cudaFuncAttributeMaxDynamicSharedMemorySize, SMEMSZ);
    cudaFuncSetAttribute(gemm_scores, cudaFuncAttributeMaxDynamicSharedMemorySize, SMEMSZ);
    cudaFuncSetAttribute(gemm_pv,     cudaFuncAttributeMaxDynamicSharedMemorySize, SMEMSZ);

    // 0) zero row sums + convert inputs to fp16
    zero_rs<<<MTOT / 1024, 1024>>>(RS);
    {
        dim3 gb((MTOT * (long)DD) / (8 * 256), 1, 3);
        cvt3_half<<<gb, 256>>>((const float4*)x, X,
                               (const float4*)y, Y,
                               (const float4*)z, Z);
        dim3 gw(((long)DD * DD) / (8 * 256), 1, 3);
        cvt3_half<<<gw, 256>>>((const float4*)Wq, W,
                               (const float4*)Wk, W + (long)DD * DD,
                               (const float4*)Wv, W + 2 * (long)DD * DD);
    }
    // 1) merged persistent QKV projections (V transposed)
    gemm_proj<<<grid, NTHR, SMEMSZ>>>(X, Y, Z, W, bq, bk, bv, Q, Kb, Vt);
    // 2) P = exp(Q K^T / 32), row sums via atomics
    gemm_scores<<<grid, NTHR, SMEMSZ>>>(Q, Kb, P, RS);
    // 3) out = (P @ Vt^T) / rowsum
    gemm_pv<<<grid, NTHR, SMEMSZ>>>(P, Vt, RS, out);
}